// round 5
// baseline (speedup 1.0000x reference)
#include <cuda_runtime.h>
#include <cuda_bf16.h>
#include <cstdint>
#include <math.h>

#define EPS 1e-5f

// ---------------- scratch (device globals; no allocation allowed) ----------------
__device__ float g_bufA[67108864];               // H (max 131072 x 512)
__device__ float g_bufB[16777216];               // GEMM2 outputs (max 32768 x 512)
__device__ __nv_bfloat16 g_ahi[67108864];        // activation hi plane
__device__ __nv_bfloat16 g_alo[67108864];        // activation lo plane
__device__ __nv_bfloat16 g_whi[1048576];         // weight hi plane (reused per GEMM)
__device__ __nv_bfloat16 g_wlo[1048576];         // weight lo plane
__device__ float g_sum[1024];
__device__ float g_sumsq[1024];
__device__ float g_scale[1024];
__device__ float g_shift[1024];

// ---------------- PTX helpers ----------------
__device__ __forceinline__ uint32_t smem_u32(const void* p) {
    uint32_t a;
    asm("{ .reg .u64 t; cvta.to.shared.u64 t, %1; cvt.u32.u64 %0, t; }" : "=r"(a) : "l"(p));
    return a;
}
__device__ __forceinline__ void cp16(uint32_t sdst, const void* gsrc) {
    asm volatile("cp.async.cg.shared.global [%0], [%1], 16;" :: "r"(sdst), "l"(gsrc));
}
#define CP_COMMIT() asm volatile("cp.async.commit_group;" ::: "memory")
#define CP_WAIT(n)  asm volatile("cp.async.wait_group %0;" :: "n"(n) : "memory")

__device__ __forceinline__ void ldsm_x4(uint32_t* r, uint32_t addr) {
    asm volatile("ldmatrix.sync.aligned.m8n8.x4.shared.b16 {%0,%1,%2,%3}, [%4];"
                 : "=r"(r[0]), "=r"(r[1]), "=r"(r[2]), "=r"(r[3]) : "r"(addr));
}
__device__ __forceinline__ void ldsm_x4_t(uint32_t* r, uint32_t addr) {
    asm volatile("ldmatrix.sync.aligned.m8n8.x4.trans.shared.b16 {%0,%1,%2,%3}, [%4];"
                 : "=r"(r[0]), "=r"(r[1]), "=r"(r[2]), "=r"(r[3]) : "r"(addr));
}
__device__ __forceinline__ void mma16816(float* d, const uint32_t* a, uint32_t b0, uint32_t b1) {
    asm volatile("mma.sync.aligned.m16n8k16.row.col.f32.bf16.bf16.f32 "
                 "{%0,%1,%2,%3}, {%4,%5,%6,%7}, {%8,%9}, {%0,%1,%2,%3};"
                 : "+f"(d[0]), "+f"(d[1]), "+f"(d[2]), "+f"(d[3])
                 : "r"(a[0]), "r"(a[1]), "r"(a[2]), "r"(a[3]), "r"(b0), "r"(b1));
}

// fp32x4 -> hi/lo bf16x4, 8B each, to global
__device__ __forceinline__ void split4g(float4 v, __nv_bfloat16* hp, __nv_bfloat16* lp) {
    __nv_bfloat162 h01 = __floats2bfloat162_rn(v.x, v.y);
    __nv_bfloat162 h23 = __floats2bfloat162_rn(v.z, v.w);
    float2 f01 = __bfloat1622float2(h01);
    float2 f23 = __bfloat1622float2(h23);
    __nv_bfloat162 l01 = __floats2bfloat162_rn(v.x - f01.x, v.y - f01.y);
    __nv_bfloat162 l23 = __floats2bfloat162_rn(v.z - f23.x, v.w - f23.y);
    uint2 hv, lv;
    hv.x = *reinterpret_cast<uint32_t*>(&h01);
    hv.y = *reinterpret_cast<uint32_t*>(&h23);
    lv.x = *reinterpret_cast<uint32_t*>(&l01);
    lv.y = *reinterpret_cast<uint32_t*>(&l23);
    *reinterpret_cast<uint2*>(hp) = hv;
    *reinterpret_cast<uint2*>(lp) = lv;
}

// ---------------- elementwise kernels ----------------
__global__ void zero_stats_kernel(int n) {
    int i = blockIdx.x * blockDim.x + threadIdx.x;
    if (i < n) { g_sum[i] = 0.f; g_sumsq[i] = 0.f; }
}

__global__ void finalize_stats_kernel(const float* __restrict__ gamma,
                                      const float* __restrict__ beta,
                                      int N, float invM) {
    int i = blockIdx.x * blockDim.x + threadIdx.x;
    if (i >= N) return;
    float mu  = g_sum[i] * invM;
    float var = g_sumsq[i] * invM - mu * mu;
    float sc  = gamma[i] * rsqrtf(var + EPS);
    g_scale[i] = sc;
    g_shift[i] = beta[i] - mu * sc;
}

// weight split, no transpose: W (K,N) fp32 -> (K,N) bf16 planes
__global__ void wsplit_kernel(const float* __restrict__ W,
                              __nv_bfloat16* __restrict__ hi, __nv_bfloat16* __restrict__ lo,
                              long long total4) {
    for (long long i = (long long)blockIdx.x * blockDim.x + threadIdx.x;
         i < total4; i += (long long)gridDim.x * blockDim.x) {
        float4 v = *(const float4*)(W + i * 4);
        split4g(v, hi + i * 4, lo + i * 4);
    }
}

// row-wise split (optional BN normalize + relu). grid.x = rows
template <bool NORM>
__global__ void split_kernel(const float* __restrict__ in,
                             __nv_bfloat16* __restrict__ hi, __nv_bfloat16* __restrict__ lo,
                             int K) {
    size_t ro = (size_t)blockIdx.x * K;
    for (int c = threadIdx.x * 4; c < K; c += blockDim.x * 4) {
        float4 v = *(const float4*)(in + ro + c);
        if (NORM) {
            v.x = fmaxf(v.x * g_scale[c + 0] + g_shift[c + 0], 0.f);
            v.y = fmaxf(v.y * g_scale[c + 1] + g_shift[c + 1], 0.f);
            v.z = fmaxf(v.z * g_scale[c + 2] + g_shift[c + 2], 0.f);
            v.w = fmaxf(v.w * g_scale[c + 3] + g_shift[c + 3], 0.f);
        }
        split4g(v, hi + ro + c, lo + ro + c);
    }
}

// gather + concat + split
__global__ void cat_split_kernel(const float* __restrict__ left,
                                 const float* __restrict__ right,
                                 const int* __restrict__ idx,
                                 __nv_bfloat16* __restrict__ hi, __nv_bfloat16* __restrict__ lo,
                                 int rows, int Cl, int Cr, int outRPB, int srcRPB) {
    int cols = Cl + Cr;
    int c4n = cols >> 2;
    long long t = (long long)blockIdx.x * blockDim.x + threadIdx.x;
    long long total = (long long)rows * c4n;
    if (t >= total) return;
    int row = (int)(t / c4n);
    int c4 = (int)(t % c4n) * 4;
    float4 v;
    if (c4 < Cl) {
        v = *(const float4*)(left + (size_t)row * Cl + c4);
    } else {
        int b = row / outRPB;
        int src = b * srcRPB + idx[row];
        v = *(const float4*)(right + (size_t)src * Cr + (c4 - Cl));
    }
    size_t o = (size_t)row * cols + c4;
    split4g(v, hi + o, lo + o);
}

// ---------------- HMMA GEMM on pre-split bf16 planes ----------------
// A planes (M,K) row-major; W planes (K,N) row-major. C = A@W + bias (fp32).
// BM=128, BN=128, BK=32; 3-product split-bf16; cp.async double-buffer.
// DO_STATS: also accumulate column sum/sumsq of C into g_sum/g_sumsq.
template <bool DO_STATS>
__global__ __launch_bounds__(256, 1)
void hmma_gemm_kernel(const __nv_bfloat16* __restrict__ Ah, const __nv_bfloat16* __restrict__ Al,
                      const __nv_bfloat16* __restrict__ Wh, const __nv_bfloat16* __restrict__ Wl,
                      const float* __restrict__ bias, float* __restrict__ C,
                      int M, int N, int K) {
    constexpr int A_STR = 80;                 // bytes per A smem row (32 bf16 + pad)
    constexpr int W_STR = 272;                // bytes per W smem row (128 bf16 + pad)
    constexpr int A_PLANE = 128 * A_STR;      // 10240
    constexpr int W_PLANE = 32 * W_STR;       // 8704
    constexpr int OFF_AH = 0;
    constexpr int OFF_AL = A_PLANE;
    constexpr int OFF_WH = 2 * A_PLANE;
    constexpr int OFF_WL = 2 * A_PLANE + W_PLANE;
    constexpr int STAGE = 2 * A_PLANE + 2 * W_PLANE;  // 37888

    extern __shared__ char sm[];
    const uint32_t smb = smem_u32(sm);

    const int tid = threadIdx.x;
    const int wid = tid >> 5;
    const int lane = tid & 31;
    const int warp_m = (wid >> 2) * 64;
    const int warp_n = (wid & 3) * 32;
    const int bm0 = blockIdx.y * 128;
    const int bn0 = blockIdx.x * 128;
    const int T = K >> 5;

    // cp.async mapping: A plane 512 chunks of 16B, W plane 512 chunks
    // thread handles chunks tid and tid+256 of each plane
    int aRow[2], aCol[2], wRow[2], wCol[2];
    uint32_t aS[2], wS[2];
#pragma unroll
    for (int i = 0; i < 2; i++) {
        int c = tid + (i << 8);
        aRow[i] = c >> 2;  aCol[i] = c & 3;
        wRow[i] = c >> 4;  wCol[i] = c & 15;
        aS[i] = aRow[i] * A_STR + aCol[i] * 16;
        wS[i] = wRow[i] * W_STR + wCol[i] * 16;
    }

    // ldmatrix offsets (stage-relative)
    uint32_t a_off[4], b_off[2];
#pragma unroll
    for (int mt = 0; mt < 4; mt++)
        a_off[mt] = (uint32_t)((warp_m + mt * 16 + (lane & 15)) * A_STR + ((lane >> 4) << 3) * 2);
#pragma unroll
    for (int np = 0; np < 2; np++)
        b_off[np] = (uint32_t)((lane & 15) * W_STR + (warp_n + np * 16 + ((lane >> 4) << 3)) * 2);

    float acc[4][4][4];
#pragma unroll
    for (int mt = 0; mt < 4; mt++)
#pragma unroll
        for (int nt = 0; nt < 4; nt++)
#pragma unroll
            for (int q = 0; q < 4; q++) acc[mt][nt][q] = 0.f;

    // issue stage 0
    {
        uint32_t sb = smb;
#pragma unroll
        for (int i = 0; i < 2; i++) {
            size_t ga = (size_t)(bm0 + aRow[i]) * K + aCol[i] * 8;
            cp16(sb + OFF_AH + aS[i], Ah + ga);
            cp16(sb + OFF_AL + aS[i], Al + ga);
            size_t gw = (size_t)wRow[i] * N + bn0 + wCol[i] * 8;
            cp16(sb + OFF_WH + wS[i], Wh + gw);
            cp16(sb + OFF_WL + wS[i], Wl + gw);
        }
        CP_COMMIT();
    }

    for (int t = 0; t < T; t++) {
        const int s = t & 1;
        const uint32_t sbase = smb + s * STAGE;
        const bool has_next = (t + 1 < T);

        if (has_next) {
            const int k0 = (t + 1) << 5;
            uint32_t nb = smb + (s ^ 1) * STAGE;
#pragma unroll
            for (int i = 0; i < 2; i++) {
                size_t ga = (size_t)(bm0 + aRow[i]) * K + k0 + aCol[i] * 8;
                cp16(nb + OFF_AH + aS[i], Ah + ga);
                cp16(nb + OFF_AL + aS[i], Al + ga);
                size_t gw = (size_t)(k0 + wRow[i]) * N + bn0 + wCol[i] * 8;
                cp16(nb + OFF_WH + wS[i], Wh + gw);
                cp16(nb + OFF_WL + wS[i], Wl + gw);
            }
            CP_COMMIT();
            CP_WAIT(1);
        } else {
            CP_WAIT(0);
        }
        __syncthreads();

#pragma unroll
        for (int ks = 0; ks < 2; ks++) {
            uint32_t ah[4][4], al[4][4], bh[2][4], bl[2][4];
#pragma unroll
            for (int mt = 0; mt < 4; mt++) {
                ldsm_x4(ah[mt], sbase + OFF_AH + a_off[mt] + ks * 32);
                ldsm_x4(al[mt], sbase + OFF_AL + a_off[mt] + ks * 32);
            }
#pragma unroll
            for (int np = 0; np < 2; np++) {
                ldsm_x4_t(bh[np], sbase + OFF_WH + b_off[np] + ks * (16 * W_STR));
                ldsm_x4_t(bl[np], sbase + OFF_WL + b_off[np] + ks * (16 * W_STR));
            }
#pragma unroll
            for (int mt = 0; mt < 4; mt++) {
#pragma unroll
                for (int nt = 0; nt < 4; nt++) {
                    const uint32_t* bhp = &bh[nt >> 1][(nt & 1) * 2];
                    const uint32_t* blp = &bl[nt >> 1][(nt & 1) * 2];
                    mma16816(acc[mt][nt], ah[mt], bhp[0], bhp[1]);
                    mma16816(acc[mt][nt], ah[mt], blp[0], blp[1]);
                    mma16816(acc[mt][nt], al[mt], bhp[0], bhp[1]);
                }
            }
        }
        __syncthreads();
    }

    // epilogue: bias + store (+ optional column stats)
#pragma unroll
    for (int nt = 0; nt < 4; nt++) {
        int c0 = bn0 + warp_n + nt * 8 + (lane & 3) * 2;
        float b0 = bias[c0], b1 = bias[c0 + 1];
        float s0 = 0.f, s1 = 0.f, q0 = 0.f, q1 = 0.f;
#pragma unroll
        for (int mt = 0; mt < 4; mt++) {
            int r0 = bm0 + warp_m + mt * 16 + (lane >> 2);
            float v0 = acc[mt][nt][0] + b0, v1 = acc[mt][nt][1] + b1;
            float v2 = acc[mt][nt][2] + b0, v3 = acc[mt][nt][3] + b1;
            float2 p0; p0.x = v0; p0.y = v1;
            float2 p1; p1.x = v2; p1.y = v3;
            *(float2*)(C + (size_t)r0 * N + c0) = p0;
            *(float2*)(C + (size_t)(r0 + 8) * N + c0) = p1;
            if (DO_STATS) {
                s0 += v0 + v2; s1 += v1 + v3;
                q0 += v0 * v0 + v2 * v2; q1 += v1 * v1 + v3 * v3;
            }
        }
        if (DO_STATS) {
#pragma unroll
            for (int off = 4; off < 32; off <<= 1) {
                s0 += __shfl_xor_sync(0xFFFFFFFFu, s0, off);
                s1 += __shfl_xor_sync(0xFFFFFFFFu, s1, off);
                q0 += __shfl_xor_sync(0xFFFFFFFFu, q0, off);
                q1 += __shfl_xor_sync(0xFFFFFFFFu, q1, off);
            }
            if ((lane >> 2) == 0) {
                atomicAdd(&g_sum[c0], s0);
                atomicAdd(&g_sum[c0 + 1], s1);
                atomicAdd(&g_sumsq[c0], q0);
                atomicAdd(&g_sumsq[c0 + 1], q1);
            }
        }
    }
}

// ---------------- host orchestration ----------------
static const int GEMM_SMEM = 2 * 37888;   // 75776

static __nv_bfloat16 *s_ahi, *s_alo, *s_whi, *s_wlo;
static float *s_bufA, *s_bufB;

static void run_gemm(const float* bias, float* C, int M, int N, int K, bool stats) {
    dim3 grid(N / 128, M / 128);
    if (stats)
        hmma_gemm_kernel<true><<<grid, 256, GEMM_SMEM>>>(s_ahi, s_alo, s_whi, s_wlo, bias, C, M, N, K);
    else
        hmma_gemm_kernel<false><<<grid, 256, GEMM_SMEM>>>(s_ahi, s_alo, s_whi, s_wlo, bias, C, M, N, K);
}

static void run_wsplit(const float* W, long long elems) {
    wsplit_kernel<<<1024, 256>>>(W, s_whi, s_wlo, elems / 4);
}

extern "C" void kernel_launch(void* const* d_in, const int* in_sizes, int n_in,
                              void* d_out, int out_size) {
    const float* f0 = (const float*)d_in[0];
    const float* f1 = (const float*)d_in[1];
    const float* f2 = (const float*)d_in[2];
    const float* up0_w1 = (const float*)d_in[3];
    const float* up0_b1 = (const float*)d_in[4];
    const float* up0_g  = (const float*)d_in[5];
    const float* up0_be = (const float*)d_in[6];
    const float* up0_w2 = (const float*)d_in[7];
    const float* up0_b2 = (const float*)d_in[8];
    const float* up1_w1 = (const float*)d_in[9];
    const float* up1_b1 = (const float*)d_in[10];
    const float* up1_g  = (const float*)d_in[11];
    const float* up1_be = (const float*)d_in[12];
    const float* up1_w2 = (const float*)d_in[13];
    const float* up1_b2 = (const float*)d_in[14];
    const float* skip0_w1 = (const float*)d_in[15];
    const float* skip0_b1 = (const float*)d_in[16];
    const float* skip0_g  = (const float*)d_in[17];
    const float* skip0_be = (const float*)d_in[18];
    const float* skip0_w2 = (const float*)d_in[19];
    const float* skip0_b2 = (const float*)d_in[20];
    const float* skip1_w1 = (const float*)d_in[21];
    const float* skip1_b1 = (const float*)d_in[22];
    const float* skip1_g  = (const float*)d_in[23];
    const float* skip1_be = (const float*)d_in[24];
    const float* skip1_w2 = (const float*)d_in[25];
    const float* skip1_b2 = (const float*)d_in[26];
    const int*   pool0 = (const int*)d_in[27];
    const int*   pool1 = (const int*)d_in[28];
    float* out = (float*)d_out;

    cudaGetSymbolAddress((void**)&s_bufA, g_bufA);
    cudaGetSymbolAddress((void**)&s_bufB, g_bufB);
    cudaGetSymbolAddress((void**)&s_ahi, g_ahi);
    cudaGetSymbolAddress((void**)&s_alo, g_alo);
    cudaGetSymbolAddress((void**)&s_whi, g_whi);
    cudaGetSymbolAddress((void**)&s_wlo, g_wlo);

    cudaFuncSetAttribute(hmma_gemm_kernel<false>, cudaFuncAttributeMaxDynamicSharedMemorySize, GEMM_SMEM);
    cudaFuncSetAttribute(hmma_gemm_kernel<true>,  cudaFuncAttributeMaxDynamicSharedMemorySize, GEMM_SMEM);

    const int B = 4;
    const int N0 = 32768, N1 = 8192, N2 = 2048;
    const int C0 = 256, C1 = 512, C2 = 1024;
    const int M_u1 = B * N2, M_s1 = B * N1, M_s0 = B * N0;

    // ---- up1 MLP: f2 (8192,1024) -> 1024 -> 512 ----
    zero_stats_kernel<<<4, 256>>>(1024);                              // app launch 0
    split_kernel<false><<<M_u1, 128>>>(f2, s_ahi, s_alo, C2);         // 1
    run_wsplit(up1_w1, (long long)C2 * C2);                           // 2
    run_gemm(up1_b1, s_bufA, M_u1, C2, C2, true);                     // 3  <- profiled slot
    finalize_stats_kernel<<<4, 256>>>(up1_g, up1_be, C2, 1.0f / M_u1);
    split_kernel<true><<<M_u1, 128>>>(s_bufA, s_ahi, s_alo, C2);
    run_wsplit(up1_w2, (long long)C2 * C1);
    run_gemm(up1_b2, s_bufB, M_u1, C1, C2, false);

    // ---- gather pool1 + concat f1 -> planes (32768,1024) ----
    {
        long long total = (long long)M_s1 * ((2 * C1) / 4);
        cat_split_kernel<<<(int)((total + 255) / 256), 256>>>(f1, s_bufB, pool1,
                                                              s_ahi, s_alo, M_s1, C1, C1, N1, N2);
    }

    // ---- skip1 MLP: (32768,1024) -> 1024 -> 512 ----
    zero_stats_kernel<<<4, 256>>>(1024);
    run_wsplit(skip1_w1, (long long)(2 * C1) * (2 * C1));
    run_gemm(skip1_b1, s_bufA, M_s1, 2 * C1, 2 * C1, true);
    finalize_stats_kernel<<<4, 256>>>(skip1_g, skip1_be, 2 * C1, 1.0f / M_s1);
    split_kernel<true><<<M_s1, 128>>>(s_bufA, s_ahi, s_alo, 2 * C1);
    run_wsplit(skip1_w2, (long long)(2 * C1) * C1);
    run_gemm(skip1_b2, s_bufB, M_s1, C1, 2 * C1, false);

    // ---- up0 MLP: (32768,512) -> 512 -> 256 ----
    split_kernel<false><<<M_s1, 128>>>(s_bufB, s_ahi, s_alo, C1);
    zero_stats_kernel<<<2, 256>>>(512);
    run_wsplit(up0_w1, (long long)C1 * C1);
    run_gemm(up0_b1, s_bufA, M_s1, C1, C1, true);
    finalize_stats_kernel<<<2, 256>>>(up0_g, up0_be, C1, 1.0f / M_s1);
    split_kernel<true><<<M_s1, 128>>>(s_bufA, s_ahi, s_alo, C1);
    run_wsplit(up0_w2, (long long)C1 * C0);
    run_gemm(up0_b2, s_bufB, M_s1, C0, C1, false);

    // ---- gather pool0 + concat f0 -> planes (131072,512) ----
    {
        long long total = (long long)M_s0 * ((2 * C0) / 4);
        cat_split_kernel<<<(int)((total + 255) / 256), 256>>>(f0, s_bufB, pool0,
                                                              s_ahi, s_alo, M_s0, C0, C0, N0, N1);
    }

    // ---- skip0 MLP: (131072,512) -> 512 -> 256 -> out ----
    zero_stats_kernel<<<2, 256>>>(512);
    run_wsplit(skip0_w1, (long long)(2 * C0) * (2 * C0));
    run_gemm(skip0_b1, s_bufA, M_s0, 2 * C0, 2 * C0, true);
    finalize_stats_kernel<<<2, 256>>>(skip0_g, skip0_be, 2 * C0, 1.0f / M_s0);
    split_kernel<true><<<M_s0, 128>>>(s_bufA, s_ahi, s_alo, 2 * C0);
    run_wsplit(skip0_w2, (long long)(2 * C0) * C0);
    run_gemm(skip0_b2, out, M_s0, C0, 2 * C0, false);
}

// round 6
// speedup vs baseline: 1.2383x; 1.2383x over previous
#include <cuda_runtime.h>
#include <cuda_bf16.h>
#include <cstdint>
#include <math.h>

#define EPS 1e-5f

// ---------------- scratch (device globals) ----------------
__device__ float g_bufA[67108864];               // GEMM1 H outputs (max 131072x512)
__device__ float g_bufB[16777216];               // GEMM2 outputs (max 32768x512)
__device__ float g_bufC[67108864];               // concat buffers (fp32)
__device__ __nv_bfloat16 g_whi[4194304];         // weight hi planes (all 8 GEMMs)
__device__ __nv_bfloat16 g_wlo[4194304];         // weight lo planes
__device__ float g_sum[1024];
__device__ float g_sumsq[1024];
__device__ float g_scale[1024];
__device__ float g_shift[1024];

// ---------------- PTX helpers ----------------
__device__ __forceinline__ uint32_t smem_u32(const void* p) {
    uint32_t a;
    asm("{ .reg .u64 t; cvta.to.shared.u64 t, %1; cvt.u32.u64 %0, t; }" : "=r"(a) : "l"(p));
    return a;
}
__device__ __forceinline__ void cp16(uint32_t sdst, const void* gsrc) {
    asm volatile("cp.async.cg.shared.global [%0], [%1], 16;" :: "r"(sdst), "l"(gsrc));
}
#define CP_COMMIT() asm volatile("cp.async.commit_group;" ::: "memory")
#define CP_WAIT0()  asm volatile("cp.async.wait_group 0;" ::: "memory")

__device__ __forceinline__ void ldsm_x4(uint32_t* r, uint32_t addr) {
    asm volatile("ldmatrix.sync.aligned.m8n8.x4.shared.b16 {%0,%1,%2,%3}, [%4];"
                 : "=r"(r[0]), "=r"(r[1]), "=r"(r[2]), "=r"(r[3]) : "r"(addr));
}
__device__ __forceinline__ void ldsm_x4_t(uint32_t* r, uint32_t addr) {
    asm volatile("ldmatrix.sync.aligned.m8n8.x4.trans.shared.b16 {%0,%1,%2,%3}, [%4];"
                 : "=r"(r[0]), "=r"(r[1]), "=r"(r[2]), "=r"(r[3]) : "r"(addr));
}
__device__ __forceinline__ void mma16816(float* d, const uint32_t* a, uint32_t b0, uint32_t b1) {
    asm volatile("mma.sync.aligned.m16n8k16.row.col.f32.bf16.bf16.f32 "
                 "{%0,%1,%2,%3}, {%4,%5,%6,%7}, {%8,%9}, {%0,%1,%2,%3};"
                 : "+f"(d[0]), "+f"(d[1]), "+f"(d[2]), "+f"(d[3])
                 : "r"(a[0]), "r"(a[1]), "r"(a[2]), "r"(a[3]), "r"(b0), "r"(b1));
}

// fp32x4 -> hi/lo bf16x4 (8B each)
__device__ __forceinline__ void split4s(float4 v, char* hp, char* lp) {
    __nv_bfloat162 h01 = __floats2bfloat162_rn(v.x, v.y);
    __nv_bfloat162 h23 = __floats2bfloat162_rn(v.z, v.w);
    float2 f01 = __bfloat1622float2(h01);
    float2 f23 = __bfloat1622float2(h23);
    __nv_bfloat162 l01 = __floats2bfloat162_rn(v.x - f01.x, v.y - f01.y);
    __nv_bfloat162 l23 = __floats2bfloat162_rn(v.z - f23.x, v.w - f23.y);
    uint2 hv, lv;
    hv.x = *reinterpret_cast<uint32_t*>(&h01);
    hv.y = *reinterpret_cast<uint32_t*>(&h23);
    lv.x = *reinterpret_cast<uint32_t*>(&l01);
    lv.y = *reinterpret_cast<uint32_t*>(&l23);
    *reinterpret_cast<uint2*>(hp) = hv;
    *reinterpret_cast<uint2*>(lp) = lv;
}

// ---------------- elementwise kernels ----------------
__global__ void zero_stats_kernel(int n) {
    int i = blockIdx.x * blockDim.x + threadIdx.x;
    if (i < n) { g_sum[i] = 0.f; g_sumsq[i] = 0.f; }
}

__global__ void finalize_stats_kernel(const float* __restrict__ gamma,
                                      const float* __restrict__ beta,
                                      int N, float invM) {
    int i = blockIdx.x * blockDim.x + threadIdx.x;
    if (i >= N) return;
    float mu  = g_sum[i] * invM;
    float var = g_sumsq[i] * invM - mu * mu;
    float sc  = gamma[i] * rsqrtf(var + EPS);
    g_scale[i] = sc;
    g_shift[i] = beta[i] - mu * sc;
}

// W (K,N) fp32 -> bf16 hi/lo planes, same layout
__global__ void wsplit_kernel(const float* __restrict__ W,
                              __nv_bfloat16* __restrict__ hi, __nv_bfloat16* __restrict__ lo,
                              long long total4) {
    for (long long i = (long long)blockIdx.x * blockDim.x + threadIdx.x;
         i < total4; i += (long long)gridDim.x * blockDim.x) {
        float4 v = *(const float4*)(W + i * 4);
        __nv_bfloat162 h01 = __floats2bfloat162_rn(v.x, v.y);
        __nv_bfloat162 h23 = __floats2bfloat162_rn(v.z, v.w);
        float2 f01 = __bfloat1622float2(h01);
        float2 f23 = __bfloat1622float2(h23);
        __nv_bfloat162 l01 = __floats2bfloat162_rn(v.x - f01.x, v.y - f01.y);
        __nv_bfloat162 l23 = __floats2bfloat162_rn(v.z - f23.x, v.w - f23.y);
        uint2 hv, lv;
        hv.x = *reinterpret_cast<uint32_t*>(&h01);
        hv.y = *reinterpret_cast<uint32_t*>(&h23);
        lv.x = *reinterpret_cast<uint32_t*>(&l01);
        lv.y = *reinterpret_cast<uint32_t*>(&l23);
        *reinterpret_cast<uint2*>(hi + i * 4) = hv;
        *reinterpret_cast<uint2*>(lo + i * 4) = lv;
    }
}

__global__ void build_cat_kernel(const float* __restrict__ left,
                                 const float* __restrict__ right,
                                 const int* __restrict__ idx,
                                 float* __restrict__ out,
                                 int rows, int Cl, int Cr,
                                 int outRowsPerBatch, int srcRowsPerBatch) {
    int cols = Cl + Cr;
    int c4n = cols >> 2;
    long long t = (long long)blockIdx.x * blockDim.x + threadIdx.x;
    long long total = (long long)rows * c4n;
    if (t >= total) return;
    int row = (int)(t / c4n);
    int c4 = (int)(t % c4n) * 4;
    float4 v;
    if (c4 < Cl) {
        v = *(const float4*)(left + (size_t)row * Cl + c4);
    } else {
        int b = row / outRowsPerBatch;
        int src = b * srcRowsPerBatch + idx[row];
        v = *(const float4*)(right + (size_t)src * Cr + (c4 - Cl));
    }
    *(float4*)(out + (size_t)row * cols + c4) = v;
}

// ---------------- HMMA GEMM ----------------
// C = f(A) @ W + bias.  A (M,K) fp32; W pre-split bf16 planes (K,N).
// f = identity or BN normalize+ReLU. STATS: accumulate column sum/sumsq of C.
// BM=128, BN=128, BK=32; split-bf16 3-product; W via cp.async, A converted in-kernel.
template <bool NORM, bool STATS>
__global__ __launch_bounds__(256, 2)
void hmma_gemm_kernel(const float* __restrict__ A,
                      const __nv_bfloat16* __restrict__ Wh, const __nv_bfloat16* __restrict__ Wl,
                      const float* __restrict__ bias, float* __restrict__ C,
                      int M, int N, int K) {
    constexpr int A_STR = 80;                 // bytes per A smem row (32 bf16 + pad)
    constexpr int W_STR = 272;                // bytes per W smem row (128 bf16 + pad)
    constexpr int A_PLANE = 128 * A_STR;      // 10240
    constexpr int W_PLANE = 32 * W_STR;       // 8704
    constexpr int OFF_AH = 0;
    constexpr int OFF_AL = A_PLANE;
    constexpr int OFF_WH = 2 * A_PLANE;
    constexpr int OFF_WL = 2 * A_PLANE + W_PLANE;
    constexpr int STAGE = 2 * A_PLANE + 2 * W_PLANE;  // 37888

    extern __shared__ char sm[];
    const uint32_t smb = smem_u32(sm);

    const int tid = threadIdx.x;
    const int wid = tid >> 5;
    const int lane = tid & 31;
    const int warp_m = (wid >> 2) * 64;
    const int warp_n = (wid & 3) * 32;
    const int bm0 = blockIdx.y * 128;
    const int bn0 = blockIdx.x * 128;
    const int T = K >> 5;

    // A fp32 LDG mapping: 128x32 = 1024 float4, 4 per thread
    int a_row[4], a_c[4];
    uint32_t a_soff[4];
#pragma unroll
    for (int i = 0; i < 4; i++) {
        int idx = tid + (i << 8);
        a_row[i] = idx >> 3;
        a_c[i] = (idx & 7) << 2;
        a_soff[i] = a_row[i] * A_STR + a_c[i] * 2;
    }
    // W cp.async mapping: 32x128 bf16 per plane = 512 x 16B chunks, 2 per thread
    int wRow[2], wCol[2];
    uint32_t wS[2];
#pragma unroll
    for (int i = 0; i < 2; i++) {
        int c = tid + (i << 8);
        wRow[i] = c >> 4;
        wCol[i] = (c & 15) * 8;
        wS[i] = wRow[i] * W_STR + (c & 15) * 16;
    }

    // ldmatrix offsets (stage-relative)
    uint32_t a_off[4], b_off[2];
#pragma unroll
    for (int mt = 0; mt < 4; mt++)
        a_off[mt] = (uint32_t)((warp_m + mt * 16 + (lane & 15)) * A_STR + ((lane >> 4) << 3) * 2);
#pragma unroll
    for (int np = 0; np < 2; np++)
        b_off[np] = (uint32_t)((lane & 15) * W_STR + (warp_n + np * 16 + ((lane >> 4) << 3)) * 2);

    float acc[4][4][4];
#pragma unroll
    for (int mt = 0; mt < 4; mt++)
#pragma unroll
        for (int nt = 0; nt < 4; nt++)
#pragma unroll
            for (int q = 0; q < 4; q++) acc[mt][nt][q] = 0.f;

    float4 ar[4];

    // ---- prologue: W cp stage0, A ldg+convert stage0 ----
    {
#pragma unroll
        for (int i = 0; i < 2; i++) {
            size_t gw = (size_t)wRow[i] * N + bn0 + wCol[i];
            cp16(smb + OFF_WH + wS[i], Wh + gw);
            cp16(smb + OFF_WL + wS[i], Wl + gw);
        }
        CP_COMMIT();
#pragma unroll
        for (int i = 0; i < 4; i++)
            ar[i] = *(const float4*)(A + (size_t)(bm0 + a_row[i]) * K + a_c[i]);
#pragma unroll
        for (int i = 0; i < 4; i++) {
            float4 v = ar[i];
            if (NORM) {
                float4 sc = *(const float4*)(g_scale + a_c[i]);
                float4 sh = *(const float4*)(g_shift + a_c[i]);
                v.x = fmaxf(v.x * sc.x + sh.x, 0.f);
                v.y = fmaxf(v.y * sc.y + sh.y, 0.f);
                v.z = fmaxf(v.z * sc.z + sh.z, 0.f);
                v.w = fmaxf(v.w * sc.w + sh.w, 0.f);
            }
            split4s(v, sm + OFF_AH + a_soff[i], sm + OFF_AL + a_soff[i]);
        }
        CP_WAIT0();
    }
    __syncthreads();

    for (int t = 0; t < T; t++) {
        const int s = t & 1;
        const uint32_t sbase = smb + s * STAGE;
        const bool has_next = (t + 1 < T);
        const int k0n = (t + 1) << 5;

        if (has_next) {
            uint32_t nb = smb + (s ^ 1) * STAGE;
#pragma unroll
            for (int i = 0; i < 2; i++) {
                size_t gw = (size_t)(k0n + wRow[i]) * N + bn0 + wCol[i];
                cp16(nb + OFF_WH + wS[i], Wh + gw);
                cp16(nb + OFF_WL + wS[i], Wl + gw);
            }
            CP_COMMIT();
#pragma unroll
            for (int i = 0; i < 4; i++)
                ar[i] = *(const float4*)(A + (size_t)(bm0 + a_row[i]) * K + k0n + a_c[i]);
        }

#pragma unroll
        for (int ks = 0; ks < 2; ks++) {
            uint32_t ah[4][4], al[4][4];
#pragma unroll
            for (int mt = 0; mt < 4; mt++) {
                ldsm_x4(ah[mt], sbase + OFF_AH + a_off[mt] + ks * 32);
                ldsm_x4(al[mt], sbase + OFF_AL + a_off[mt] + ks * 32);
            }
#pragma unroll
            for (int np = 0; np < 2; np++) {
                uint32_t bh[4], bl[4];
                ldsm_x4_t(bh, sbase + OFF_WH + b_off[np] + ks * (16 * W_STR));
                ldsm_x4_t(bl, sbase + OFF_WL + b_off[np] + ks * (16 * W_STR));
#pragma unroll
                for (int mt = 0; mt < 4; mt++) {
#pragma unroll
                    for (int half = 0; half < 2; half++) {
                        int nt = np * 2 + half;
                        mma16816(acc[mt][nt], ah[mt], bh[half * 2], bh[half * 2 + 1]);
                        mma16816(acc[mt][nt], ah[mt], bl[half * 2], bl[half * 2 + 1]);
                        mma16816(acc[mt][nt], al[mt], bh[half * 2], bh[half * 2 + 1]);
                    }
                }
            }
        }

        if (has_next) {
            char* nb = sm + (s ^ 1) * STAGE;
#pragma unroll
            for (int i = 0; i < 4; i++) {
                float4 v = ar[i];
                if (NORM) {
                    float4 sc = *(const float4*)(g_scale + k0n + a_c[i]);
                    float4 sh = *(const float4*)(g_shift + k0n + a_c[i]);
                    v.x = fmaxf(v.x * sc.x + sh.x, 0.f);
                    v.y = fmaxf(v.y * sc.y + sh.y, 0.f);
                    v.z = fmaxf(v.z * sc.z + sh.z, 0.f);
                    v.w = fmaxf(v.w * sc.w + sh.w, 0.f);
                }
                split4s(v, nb + OFF_AH + a_soff[i], nb + OFF_AL + a_soff[i]);
            }
            CP_WAIT0();
        }
        __syncthreads();
    }

    // ---- epilogue: bias + store (+ column stats) ----
    // NOTE (epilogue mapping): nt maps to b_off pairs: col = warp_n + (nt>>1)*16 + (nt&1)*8
#pragma unroll
    for (int nt = 0; nt < 4; nt++) {
        int c0 = bn0 + warp_n + (nt >> 1) * 16 + (nt & 1) * 8 + (lane & 3) * 2;
        float b0 = bias[c0], b1 = bias[c0 + 1];
        float s0 = 0.f, s1 = 0.f, q0 = 0.f, q1 = 0.f;
#pragma unroll
        for (int mt = 0; mt < 4; mt++) {
            int r0 = bm0 + warp_m + mt * 16 + (lane >> 2);
            float v0 = acc[mt][nt][0] + b0, v1 = acc[mt][nt][1] + b1;
            float v2 = acc[mt][nt][2] + b0, v3 = acc[mt][nt][3] + b1;
            float2 p0; p0.x = v0; p0.y = v1;
            float2 p1; p1.x = v2; p1.y = v3;
            *(float2*)(C + (size_t)r0 * N + c0) = p0;
            *(float2*)(C + (size_t)(r0 + 8) * N + c0) = p1;
            if (STATS) {
                s0 += v0 + v2; s1 += v1 + v3;
                q0 += v0 * v0 + v2 * v2; q1 += v1 * v1 + v3 * v3;
            }
        }
        if (STATS) {
#pragma unroll
            for (int off = 4; off < 32; off <<= 1) {
                s0 += __shfl_xor_sync(0xFFFFFFFFu, s0, off);
                s1 += __shfl_xor_sync(0xFFFFFFFFu, s1, off);
                q0 += __shfl_xor_sync(0xFFFFFFFFu, q0, off);
                q1 += __shfl_xor_sync(0xFFFFFFFFu, q1, off);
            }
            if ((lane >> 2) == 0) {
                atomicAdd(&g_sum[c0], s0);
                atomicAdd(&g_sum[c0 + 1], s1);
                atomicAdd(&g_sumsq[c0], q0);
                atomicAdd(&g_sumsq[c0 + 1], q1);
            }
        }
    }
}

// ---------------- host orchestration ----------------
static const int GEMM_SMEM = 2 * 37888;   // 75776

static __nv_bfloat16 *s_whi, *s_wlo;
static float *s_bufA, *s_bufB, *s_bufC;

template <bool NORM, bool STATS>
static void run_gemm(const float* A, size_t woff, const float* bias, float* C,
                     int M, int N, int K) {
    dim3 grid(N / 128, M / 128);
    hmma_gemm_kernel<NORM, STATS><<<grid, 256, GEMM_SMEM>>>(A, s_whi + woff, s_wlo + woff,
                                                            bias, C, M, N, K);
}

extern "C" void kernel_launch(void* const* d_in, const int* in_sizes, int n_in,
                              void* d_out, int out_size) {
    const float* f0 = (const float*)d_in[0];
    const float* f1 = (const float*)d_in[1];
    const float* f2 = (const float*)d_in[2];
    const float* up0_w1 = (const float*)d_in[3];
    const float* up0_b1 = (const float*)d_in[4];
    const float* up0_g  = (const float*)d_in[5];
    const float* up0_be = (const float*)d_in[6];
    const float* up0_w2 = (const float*)d_in[7];
    const float* up0_b2 = (const float*)d_in[8];
    const float* up1_w1 = (const float*)d_in[9];
    const float* up1_b1 = (const float*)d_in[10];
    const float* up1_g  = (const float*)d_in[11];
    const float* up1_be = (const float*)d_in[12];
    const float* up1_w2 = (const float*)d_in[13];
    const float* up1_b2 = (const float*)d_in[14];
    const float* skip0_w1 = (const float*)d_in[15];
    const float* skip0_b1 = (const float*)d_in[16];
    const float* skip0_g  = (const float*)d_in[17];
    const float* skip0_be = (const float*)d_in[18];
    const float* skip0_w2 = (const float*)d_in[19];
    const float* skip0_b2 = (const float*)d_in[20];
    const float* skip1_w1 = (const float*)d_in[21];
    const float* skip1_b1 = (const float*)d_in[22];
    const float* skip1_g  = (const float*)d_in[23];
    const float* skip1_be = (const float*)d_in[24];
    const float* skip1_w2 = (const float*)d_in[25];
    const float* skip1_b2 = (const float*)d_in[26];
    const int*   pool0 = (const int*)d_in[27];
    const int*   pool1 = (const int*)d_in[28];
    float* out = (float*)d_out;

    cudaGetSymbolAddress((void**)&s_bufA, g_bufA);
    cudaGetSymbolAddress((void**)&s_bufB, g_bufB);
    cudaGetSymbolAddress((void**)&s_bufC, g_bufC);
    cudaGetSymbolAddress((void**)&s_whi, g_whi);
    cudaGetSymbolAddress((void**)&s_wlo, g_wlo);

    cudaFuncSetAttribute(hmma_gemm_kernel<false, true>, cudaFuncAttributeMaxDynamicSharedMemorySize, GEMM_SMEM);
    cudaFuncSetAttribute(hmma_gemm_kernel<true, false>, cudaFuncAttributeMaxDynamicSharedMemorySize, GEMM_SMEM);

    const int B = 4;
    const int N0 = 32768, N1 = 8192, N2 = 2048;
    const int C0 = 256, C1 = 512, C2 = 1024;
    const int M_u1 = B * N2, M_s1 = B * N1, M_s0 = B * N0;

    // weight plane offsets (K,N) layout
    const size_t O_U1W1 = 0;
    const size_t O_U1W2 = 1048576;
    const size_t O_S1W1 = 1572864;
    const size_t O_S1W2 = 2621440;
    const size_t O_U0W1 = 3145728;
    const size_t O_U0W2 = 3407872;
    const size_t O_S0W1 = 3538944;
    const size_t O_S0W2 = 3801088;

    // ---- up1 MLP: f2 (8192,1024) -> 1024 -> 512 ----
    zero_stats_kernel<<<4, 256>>>(1024);
    wsplit_kernel<<<512, 256>>>(up1_w1, s_whi + O_U1W1, s_wlo + O_U1W1, (long long)C2 * C2 / 4);
    wsplit_kernel<<<512, 256>>>(up1_w2, s_whi + O_U1W2, s_wlo + O_U1W2, (long long)C2 * C1 / 4);
    run_gemm<false, true>(f2, O_U1W1, up1_b1, s_bufA, M_u1, C2, C2);     // profiled slot
    finalize_stats_kernel<<<4, 256>>>(up1_g, up1_be, C2, 1.0f / M_u1);
    run_gemm<true, false>(s_bufA, O_U1W2, up1_b2, s_bufB, M_u1, C1, C2);

    // ---- gather pool1 + concat f1 -> bufC (32768,1024) ----
    {
        long long total = (long long)M_s1 * ((2 * C1) / 4);
        build_cat_kernel<<<(int)((total + 255) / 256), 256>>>(f1, s_bufB, pool1, s_bufC,
                                                              M_s1, C1, C1, N1, N2);
    }

    // ---- skip1 MLP: (32768,1024) -> 1024 -> 512 ----
    zero_stats_kernel<<<4, 256>>>(1024);
    wsplit_kernel<<<512, 256>>>(skip1_w1, s_whi + O_S1W1, s_wlo + O_S1W1, (long long)(2 * C1) * (2 * C1) / 4);
    wsplit_kernel<<<512, 256>>>(skip1_w2, s_whi + O_S1W2, s_wlo + O_S1W2, (long long)(2 * C1) * C1 / 4);
    run_gemm<false, true>(s_bufC, O_S1W1, skip1_b1, s_bufA, M_s1, 2 * C1, 2 * C1);
    finalize_stats_kernel<<<4, 256>>>(skip1_g, skip1_be, 2 * C1, 1.0f / M_s1);
    run_gemm<true, false>(s_bufA, O_S1W2, skip1_b2, s_bufB, M_s1, C1, 2 * C1);

    // ---- up0 MLP: (32768,512) -> 512 -> 256 ----
    zero_stats_kernel<<<2, 256>>>(512);
    wsplit_kernel<<<256, 256>>>(up0_w1, s_whi + O_U0W1, s_wlo + O_U0W1, (long long)C1 * C1 / 4);
    wsplit_kernel<<<256, 256>>>(up0_w2, s_whi + O_U0W2, s_wlo + O_U0W2, (long long)C1 * C0 / 4);
    run_gemm<false, true>(s_bufB, O_U0W1, up0_b1, s_bufA, M_s1, C1, C1);
    finalize_stats_kernel<<<2, 256>>>(up0_g, up0_be, C1, 1.0f / M_s1);
    run_gemm<true, false>(s_bufA, O_U0W2, up0_b2, s_bufB, M_s1, C0, C1);

    // ---- gather pool0 + concat f0 -> bufC (131072,512) ----
    {
        long long total = (long long)M_s0 * ((2 * C0) / 4);
        build_cat_kernel<<<(int)((total + 255) / 256), 256>>>(f0, s_bufB, pool0, s_bufC,
                                                              M_s0, C0, C0, N0, N1);
    }

    // ---- skip0 MLP: (131072,512) -> 512 -> 256 -> out ----
    zero_stats_kernel<<<2, 256>>>(512);
    wsplit_kernel<<<256, 256>>>(skip0_w1, s_whi + O_S0W1, s_wlo + O_S0W1, (long long)(2 * C0) * (2 * C0) / 4);
    wsplit_kernel<<<256, 256>>>(skip0_w2, s_whi + O_S0W2, s_wlo + O_S0W2, (long long)(2 * C0) * C0 / 4);
    run_gemm<false, true>(s_bufC, O_S0W1, skip0_b1, s_bufA, M_s0, 2 * C0, 2 * C0);
    finalize_stats_kernel<<<2, 256>>>(skip0_g, skip0_be, 2 * C0, 1.0f / M_s0);
    run_gemm<true, false>(s_bufA, O_S0W2, skip0_b2, out, M_s0, C0, 2 * C0);
}